// round 14
// baseline (speedup 1.0000x reference)
#include <cuda_runtime.h>

// KAN_Convolutional_Layer: B=8, CIN=4, H=W=64, OUT=8, K2=9, G=8, Ho=Wo=62
// R14 = R13 with output-channel split across warp halves:
//   512 threads/block (grid 128): warps 0-7 -> outputs 0-3, warps 8-15 -> 4-7.
//   Per-warp LDS patterns identical to R13 (8x16B weight lines, 8-px strips,
//   8-way cg split, PSTR=368/WCG=144); per-thread serial work halved ->
//   4 warps/SMSP to cover stalls. All 32 t-planes in dynamic smem, ONE barrier.

#define B_    8
#define CIN_  4
#define H_    64
#define W_    64
#define OUT_  8
#define K2_   9
#define G_    8
#define HO_   62
#define WO_   62
#define R2_   39.0625f     // R^2 folded into weights

#define TILW  36           // 32 px + 2 halo + 2 pad (float4 alignment)
#define TILH  10
#define NPOS  (TILH*TILW)  // 360
#define PSTR  368          // empirical best plane stride
#define WCG   144          // empirical best dup'd-weight stride (9*16)
#define NTHR  512

#define TSH_F (32 * PSTR)            // 11776 floats
#define WSH_F (32 * WCG)             //  4608 floats
#define SMEM_BYTES ((TSH_F + WSH_F + 8) * 4)   // 65568 B

typedef unsigned long long u64;

__device__ __forceinline__ u64 pack2(float lo, float hi) {
    u64 r;
    asm("mov.b64 %0, {%1, %2};" : "=l"(r) : "f"(lo), "f"(hi));
    return r;
}
__device__ __forceinline__ void unpack2(u64 v, float& lo, float& hi) {
    asm("mov.b64 {%0, %1}, %2;" : "=f"(lo), "=f"(hi) : "l"(v));
}
__device__ __forceinline__ u64 fma2(u64 a, u64 b, u64 c) {
    u64 d;
    asm("fma.rn.f32x2 %0, %1, %2, %3;" : "=l"(d) : "l"(a), "l"(b), "l"(c));
    return d;
}
__device__ __forceinline__ u64 add2(u64 a, u64 b) {
    u64 d;
    asm("add.rn.f32x2 %0, %1, %2;" : "=l"(d) : "l"(a), "l"(b));
    return d;
}

__global__ void __launch_bounds__(NTHR, 1)
kan_fused_kernel(const float* __restrict__ x,
                 const float* __restrict__ phase_low,
                 const float* __restrict__ phase_high,
                 const float* __restrict__ weight,
                 const float* __restrict__ bias,
                 float* __restrict__ out) {
    extern __shared__ __align__(16) float smem[];
    float* tsh = smem;                 // 32 planes x PSTR
    float* wsh = smem + TSH_F;         // dup'd weights
    float* bsh = wsh + WSH_F;          // bias sums

    const int b   = blockIdx.z;
    const int x0  = blockIdx.x * 32;
    const int y0  = blockIdx.y * 8;
    const int tid = threadIdx.x;

    // ======== prologue: issue ALL global loads up front ========
    // x values: 3 per thread (4 c-planes x 360 positions = 1440)
    float xreg[3];
#pragma unroll
    for (int it = 0; it < 3; it++) {
        int i = tid + it * NTHR;
        float xv = 0.0f;
        if (i < CIN_ * NPOS) {
            int c   = i / NPOS;
            int pos = i - c * NPOS;
            int row = pos / TILW;
            int col = pos - row * TILW;
            int gy = y0 + row, gx = x0 + col;
            if (gy < H_ && gx < W_)
                xv = __ldg(&x[((b * CIN_ + c) * H_ + gy) * W_ + gx]);
        }
        xreg[it] = xv;
    }

    // weights, coalesced LDG: flat i = o*288 + c*72 + f*8 + g
#pragma unroll
    for (int it = 0; it < 5; it++) {
        int i = tid + it * NTHR;
        if (i < 32 * K2_ * OUT_) {
            float wv = __ldg(&weight[i]) * R2_;
            int g  = i & 7;
            int f  = (i >> 3) % K2_;
            int c  = (i / 72) & 3;
            int o  = i / 288;
            int cg = c * 8 + g;
            int base = cg * WCG + f * 16 + o * 2;
            wsh[base]     = wv;
            wsh[base + 1] = wv;
        }
    }
    if (tid < OUT_) {
        float s = 0.0f;
#pragma unroll
        for (int c = 0; c < CIN_; c++) s += bias[tid * CIN_ + c];
        bsh[tid] = s;
    }

    float pl[G_];
#pragma unroll
    for (int g = 0; g < G_; g++)
        pl[g] = __ldg(&phase_low[g]);   // broadcast over (o,c,f); ph = pl + 0.8

    // ---- spline fill, all 32 planes (from registers; no DRAM wait)
#pragma unroll
    for (int it = 0; it < 3; it++) {
        int i = tid + it * NTHR;
        if (i < CIN_ * NPOS) {
            int c   = i / NPOS;
            int pos = i - c * NPOS;
            float xv = xreg[it];
#pragma unroll
            for (int g = 0; g < G_; g++) {
                float a = xv - pl[g];
                float d = 0.8f - a;                 // == ph[g] - xv
                float m = fmaxf(a * d, 0.0f);       // relu(a)*relu(d) support
                tsh[(c * G_ + g) * PSTR + pos] = m * m;   // R^2 in weights
            }
        }
    }
    __syncthreads();   // the ONLY barrier

    // ---- lane decomposition
    const int w     = tid >> 5;          // warp 0..15
    const int l     = tid & 31;
    const int ohalf = w >> 3;            // 0: outputs 0-3, 1: outputs 4-7
    const int wl    = w & 7;
    const int q     = l >> 2;            // 0..7 (cg group) -> planes q+8k
    const int sub   = l & 3;
    const int strip = wl * 4 + sub;      // 0..31 (8-px strips)
    const int sy    = strip >> 2;        // row 0..7
    const int sxs   = strip & 3;         // strip col 0..3 -> px 8*sxs..8*sxs+7

    u64 acc[16];                         // [ol*4 + px_pair], ol = local output
#pragma unroll
    for (int k = 0; k < 16; k++) acc[k] = 0;

    // ---- conv: 12 (plane, fi) iterations, double-buffered, no seams
    float4 va[2], vb[2];
    float2 vc[2];
    ulonglong2 wv[2][6];

    const int wofs = 8 * ohalf;          // float offset to this half's outputs

    auto loadIter = [&](int j, int bi) {
        const int p  = q + 8 * (j / 3);              // planes q, q+8, q+16, q+24
        const int fi = j % 3;
        const float* pb = tsh + p * PSTR + (sy + fi) * TILW + 8 * sxs;
        va[bi] = *reinterpret_cast<const float4*>(pb);
        vb[bi] = *reinterpret_cast<const float4*>(pb + 4);
        vc[bi] = *reinterpret_cast<const float2*>(pb + 8);
        const float* wbase = wsh + p * WCG + fi * 3 * 16 + wofs;
#pragma unroll
        for (int fj = 0; fj < 3; fj++) {
            wv[bi][fj * 2 + 0] =
                *reinterpret_cast<const ulonglong2*>(wbase + fj * 16);
            wv[bi][fj * 2 + 1] =
                *reinterpret_cast<const ulonglong2*>(wbase + fj * 16 + 4);
        }
    };

    auto computeIter = [&](int bi) {
        u64 e0 = pack2(va[bi].x, va[bi].y);
        u64 e1 = pack2(va[bi].z, va[bi].w);
        u64 e2 = pack2(vb[bi].x, vb[bi].y);
        u64 e3 = pack2(vb[bi].z, vb[bi].w);
        u64 e4 = pack2(vc[bi].x, vc[bi].y);
        u64 o0 = pack2(va[bi].y, va[bi].z);
        u64 o1 = pack2(va[bi].w, vb[bi].x);
        u64 o2 = pack2(vb[bi].y, vb[bi].z);
        u64 o3 = pack2(vb[bi].w, vc[bi].x);
        u64 pj[3][4] = {{e0, e1, e2, e3},    // fj = 0
                        {o0, o1, o2, o3},    // fj = 1
                        {e1, e2, e3, e4}};   // fj = 2
#pragma unroll
        for (int fj = 0; fj < 3; fj++) {
            u64 wd[4] = {wv[bi][fj * 2 + 0].x, wv[bi][fj * 2 + 0].y,
                         wv[bi][fj * 2 + 1].x, wv[bi][fj * 2 + 1].y};
#pragma unroll
            for (int ol = 0; ol < 4; ol++) {
#pragma unroll
                for (int k = 0; k < 4; k++)
                    acc[ol * 4 + k] = fma2(pj[fj][k], wd[ol], acc[ol * 4 + k]);
            }
        }
    };

    loadIter(0, 0);
#pragma unroll
    for (int j = 0; j < 12; j++) {
        if (j < 11) loadIter(j + 1, (j + 1) & 1);
        computeIter(j & 1);
    }

    // ---- 3-level butterfly half-exchange over the 8 q-groups (16 accs)
    // consumes index bits 3,2,1 (ol_hi, ol_lo, khi) <-> q bits 0,1,2
#pragma unroll
    for (int lvl = 0; lvl < 3; lvl++) {
        const int mask = 4 << lvl;
        const int half = 8 >> lvl;
        const bool bit = (q >> lvl) & 1;
#pragma unroll
        for (int j = 0; j < 8; j++) {
            if (j < half) {
                u64 lo = acc[j], hi = acc[half + j];
                u64 sent = bit ? lo : hi;
                u64 rec  = __shfl_xor_sync(0xffffffffu, sent, mask);
                acc[j] = add2(bit ? hi : lo, rec);
            }
        }
    }
    // lane q holds acc[0] = (px0,px1), acc[1] = (px2,px3) of:
    //   ol = (q bit0 -> ol_hi, q bit1 -> ol_lo), khi = q bit2 -> px block
    const int ol  = ((q & 1) << 1) | ((q >> 1) & 1);
    const int khi = (q >> 2) & 1;
    const int o   = 4 * ohalf + ol;

    const float bo = bsh[o];
    const int oy  = y0 + sy;
    const int ox0 = x0 + 8 * sxs + 4 * khi;
    if (oy < HO_) {
        float* op = out + ((b * OUT_ + o) * HO_ + oy) * WO_;
        float v0, v1, v2, v3;
        unpack2(acc[0], v0, v1);
        unpack2(acc[1], v2, v3);
        if (ox0 + 1 < WO_)
            *reinterpret_cast<float2*>(op + ox0) = make_float2(v0 + bo, v1 + bo);
        else if (ox0 < WO_)
            op[ox0] = v0 + bo;
        if (ox0 + 3 < WO_)
            *reinterpret_cast<float2*>(op + ox0 + 2) = make_float2(v2 + bo, v3 + bo);
        else if (ox0 + 2 < WO_)
            op[ox0 + 2] = v2 + bo;
    }
}

// ---------------------------------------------------------------------------
extern "C" void kernel_launch(void* const* d_in, const int* in_sizes, int n_in,
                              void* d_out, int out_size) {
    const float* x          = (const float*)d_in[0];
    const float* phase_low  = (const float*)d_in[1];
    const float* phase_high = (const float*)d_in[2];
    const float* weight     = (const float*)d_in[3];
    const float* bias       = (const float*)d_in[4];
    float* out = (float*)d_out;

    static int attr_set = 0;   // idempotent host-side attribute (no device alloc)
    if (!attr_set) {
        cudaFuncSetAttribute(kan_fused_kernel,
                             cudaFuncAttributeMaxDynamicSharedMemorySize,
                             SMEM_BYTES);
        attr_set = 1;
    }

    dim3 grid(2, 8, B_);                 // 128 blocks x 512 threads, 1 block/SM
    kan_fused_kernel<<<grid, NTHR, SMEM_BYTES>>>(x, phase_low, phase_high,
                                                 weight, bias, out);
}

// round 15
// speedup vs baseline: 1.1667x; 1.1667x over previous
#include <cuda_runtime.h>
#include <cstdint>

// KAN_Convolutional_Layer: B=8, CIN=4, H=W=64, OUT=8, K2=9, G=8, Ho=Wo=62
// R15: tensor-core rewrite. conv == GEMM (M=30752 px, N=8 out, K=288=(32 cg x 9 f))
//   -> mma.sync.m16n8k8 tf32 with 3xTF32 hi/lo split (~fp32 accuracy).
//   128 blocks x 256 threads, tile 32x8 px. Spline t-planes stored as
//   hi/lo tf32 pairs (PSTR=360 -> conflict-free A fragments); weights as
//   hi/lo [plane][f][o] tables (conflict-free B fragments). One barrier.
//   Per warp: one px row, two 16-px M-tiles interleaved across 36 K-steps.

#define B_    8
#define CIN_  4
#define H_    64
#define W_    64
#define OUT_  8
#define K2_   9
#define G_    8
#define HO_   62
#define WO_   62
#define R2_   39.0625f     // R^2 folded into weights

#define TILW  36
#define TILH  10
#define NPOS  (TILH*TILW)  // 360
#define PSTR  360          // == NPOS; 360 % 32 == 8 -> A-frag banks 8*tg+gid all distinct
#define NTHR  256

#define TSH_F (32 * PSTR)                    // 11520 floats per copy
#define WHF   (32 * K2_ * OUT_)              // 2304 floats per copy
#define SMEM_FLOATS (2 * TSH_F + 2 * WHF + 8)
#define SMEM_BYTES  (SMEM_FLOATS * 4)        // 110,624 B

__device__ __forceinline__ uint32_t f2tf32(float v) {
    uint32_t r;
    asm("cvt.rna.tf32.f32 %0, %1;" : "=r"(r) : "f"(v));
    return r;
}

__device__ __forceinline__ void mma_tf32(float& c0, float& c1, float& c2, float& c3,
                                         uint32_t a0, uint32_t a1, uint32_t a2, uint32_t a3,
                                         uint32_t b0, uint32_t b1) {
    asm volatile(
        "mma.sync.aligned.m16n8k8.row.col.f32.tf32.tf32.f32 "
        "{%0,%1,%2,%3},{%4,%5,%6,%7},{%8,%9},{%0,%1,%2,%3};"
        : "+f"(c0), "+f"(c1), "+f"(c2), "+f"(c3)
        : "r"(a0), "r"(a1), "r"(a2), "r"(a3), "r"(b0), "r"(b1));
}

__global__ void __launch_bounds__(NTHR, 1)
kan_fused_kernel(const float* __restrict__ x,
                 const float* __restrict__ phase_low,
                 const float* __restrict__ phase_high,
                 const float* __restrict__ weight,
                 const float* __restrict__ bias,
                 float* __restrict__ out) {
    extern __shared__ __align__(16) float smem[];
    float* th  = smem;                 // t-planes, tf32 hi
    float* tl  = th + TSH_F;           // t-planes, tf32 lo
    float* wh  = tl + TSH_F;           // weights*R^2, tf32 hi  [plane][f][o]
    float* wl  = wh + WHF;             // weights*R^2, tf32 lo
    float* bsh = wl + WHF;             // bias sums

    const int b   = blockIdx.z;
    const int x0  = blockIdx.x * 32;
    const int y0  = blockIdx.y * 8;
    const int tid = threadIdx.x;

    // ======== prologue: all global loads up front ========
    float xreg[6];
#pragma unroll
    for (int it = 0; it < 6; it++) {
        int i = tid + it * NTHR;
        float xv = 0.0f;
        if (i < CIN_ * NPOS) {
            int c   = i / NPOS;
            int pos = i - c * NPOS;
            int row = pos / TILW;
            int col = pos - row * TILW;
            int gy = y0 + row, gx = x0 + col;
            if (gy < H_ && gx < W_)
                xv = __ldg(&x[((b * CIN_ + c) * H_ + gy) * W_ + gx]);
        }
        xreg[it] = xv;
    }

    // weights, coalesced: flat i = o*288 + c*72 + f*8 + g; dst = plane*72 + f*8 + o
#pragma unroll
    for (int it = 0; it < 9; it++) {
        int i = tid + it * NTHR;
        if (i < WHF) {
            float wv = __ldg(&weight[i]) * R2_;
            int g  = i & 7;
            int f  = (i >> 3) % K2_;
            int c  = (i / 72) & 3;
            int o  = i / 288;
            int dst = (c * 8 + g) * (K2_ * OUT_) + f * OUT_ + o;
            uint32_t hi = f2tf32(wv);
            float lof = wv - __uint_as_float(hi);
            wh[dst] = __uint_as_float(hi);
            wl[dst] = __uint_as_float(f2tf32(lof));
        }
    }
    if (tid < OUT_) {
        float s = 0.0f;
#pragma unroll
        for (int c = 0; c < CIN_; c++) s += bias[tid * CIN_ + c];
        bsh[tid] = s;
    }

    float pl[G_];
#pragma unroll
    for (int g = 0; g < G_; g++)
        pl[g] = __ldg(&phase_low[g]);   // broadcast arrays; ph = pl + 0.8

    // ---- spline fill, hi/lo tf32 split (from registers; no DRAM wait)
#pragma unroll
    for (int it = 0; it < 6; it++) {
        int i = tid + it * NTHR;
        if (i < CIN_ * NPOS) {
            int c   = i / NPOS;
            int pos = i - c * NPOS;
            float xv = xreg[it];
#pragma unroll
            for (int g = 0; g < G_; g++) {
                float a = xv - pl[g];
                float d = 0.8f - a;
                float m = fmaxf(a * d, 0.0f);
                float t = m * m;                       // R^2 lives in weights
                uint32_t hi = f2tf32(t);
                float lof = t - __uint_as_float(hi);
                int idx = (c * G_ + g) * PSTR + pos;
                th[idx] = __uint_as_float(hi);
                tl[idx] = __uint_as_float(f2tf32(lof));
            }
        }
    }
    __syncthreads();   // the ONLY barrier

    // ---- GEMM via mma.m16n8k8 tf32, 3xTF32
    const int w   = tid >> 5;            // warp 0..7 -> output row y0+w
    const int l   = tid & 31;
    const int gid = l >> 2;              // fragment "groupID" (px offset / o)
    const int tg  = l & 3;               // fragment "threadID_in_group" (k)

    // A-fragment lane constants: addr = plane*PSTR + (w+fi)*TILW + px + fj
    //   a0: plane = pg*8+tg, px = h*16+gid;  a1: px+8;  a2/a3: plane+4
    const int ac0 = tg * PSTR + w * TILW + gid;        // h = 0 tile
    const int ac1 = ac0 + 16;                          // h = 1 tile
    // B-fragment: addr = (pg*8+tg)*72 + f*8 + gid; b1 = +4 planes = +288
    const int bc  = tg * (K2_ * OUT_) + gid;

    float acc[2][4] = {{0.f, 0.f, 0.f, 0.f}, {0.f, 0.f, 0.f, 0.f}};

#pragma unroll
    for (int pg = 0; pg < 4; pg++) {     // plane group = input channel
#pragma unroll
        for (int f = 0; f < 9; f++) {    // filter tap fi*3+fj
            const int fi = f / 3, fj = f % 3;
            const int ao = pg * (8 * PSTR) + fi * TILW + fj;
            const int bo = pg * (8 * K2_ * OUT_) + f * OUT_;

            uint32_t bh0 = __float_as_uint(wh[bc + bo]);
            uint32_t bh1 = __float_as_uint(wh[bc + bo + 4 * K2_ * OUT_]);
            uint32_t bl0 = __float_as_uint(wl[bc + bo]);
            uint32_t bl1 = __float_as_uint(wl[bc + bo + 4 * K2_ * OUT_]);

#pragma unroll
            for (int h = 0; h < 2; h++) {
                const int a = (h ? ac1 : ac0) + ao;
                uint32_t ah0 = __float_as_uint(th[a]);
                uint32_t ah1 = __float_as_uint(th[a + 8]);
                uint32_t ah2 = __float_as_uint(th[a + 4 * PSTR]);
                uint32_t ah3 = __float_as_uint(th[a + 4 * PSTR + 8]);
                uint32_t al0 = __float_as_uint(tl[a]);
                uint32_t al1 = __float_as_uint(tl[a + 8]);
                uint32_t al2 = __float_as_uint(tl[a + 4 * PSTR]);
                uint32_t al3 = __float_as_uint(tl[a + 4 * PSTR + 8]);

                mma_tf32(acc[h][0], acc[h][1], acc[h][2], acc[h][3],
                         ah0, ah1, ah2, ah3, bh0, bh1);   // hi*hi
                mma_tf32(acc[h][0], acc[h][1], acc[h][2], acc[h][3],
                         al0, al1, al2, al3, bh0, bh1);   // lo*hi
                mma_tf32(acc[h][0], acc[h][1], acc[h][2], acc[h][3],
                         ah0, ah1, ah2, ah3, bl0, bl1);   // hi*lo
            }
        }
    }

    // ---- epilogue: C fragment -> out (+bias), guarded
    // c0: (px = h*16+gid,   o = 2*tg), c1: o+1, c2: px+8 o, c3: px+8 o+1
    const int oy = y0 + w;
    if (oy < HO_) {
        const int o0 = 2 * tg;
        const float b0v = bsh[o0];
        const float b1v = bsh[o0 + 1];
        const long strideO = (long)HO_ * WO_;
        float* baseA = out + ((long)(b * OUT_ + o0) * HO_ + oy) * WO_;
        float* baseB = baseA + strideO;   // o0+1
#pragma unroll
        for (int h = 0; h < 2; h++) {
            int px0 = x0 + h * 16 + gid;
            int px1 = px0 + 8;
            if (px0 < WO_) {
                baseA[px0] = acc[h][0] + b0v;
                baseB[px0] = acc[h][1] + b1v;
            }
            if (px1 < WO_) {
                baseA[px1] = acc[h][2] + b0v;
                baseB[px1] = acc[h][3] + b1v;
            }
        }
    }
}

// ---------------------------------------------------------------------------
extern "C" void kernel_launch(void* const* d_in, const int* in_sizes, int n_in,
                              void* d_out, int out_size) {
    const float* x          = (const float*)d_in[0];
    const float* phase_low  = (const float*)d_in[1];
    const float* phase_high = (const float*)d_in[2];
    const float* weight     = (const float*)d_in[3];
    const float* bias       = (const float*)d_in[4];
    float* out = (float*)d_out;

    static int attr_set = 0;   // idempotent host-side attribute (no device alloc)
    if (!attr_set) {
        cudaFuncSetAttribute(kan_fused_kernel,
                             cudaFuncAttributeMaxDynamicSharedMemorySize,
                             SMEM_BYTES);
        attr_set = 1;
    }

    dim3 grid(2, 8, B_);                 // 128 blocks x 256 threads
    kan_fused_kernel<<<grid, NTHR, SMEM_BYTES>>>(x, phase_low, phase_high,
                                                 weight, bias, out);
}

// round 16
// speedup vs baseline: 1.1910x; 1.0209x over previous
#include <cuda_runtime.h>
#include <cstdint>

// KAN_Convolutional_Layer: B=8, CIN=4, H=W=64, OUT=8, K2=9, G=8, Ho=Wo=62
// R16 = R15 (3xTF32 tensor-core GEMM) with the two 16-px M-tiles split
// across warp halves: 512 threads / 16 warps, warps 0-7 -> h=0, 8-15 -> h=1.
// Per-warp work halves, 4 warps/SMSP for latency coverage. Everything else
// (hi/lo split planes, PSTR=360, one barrier, coalesced weight LDG) verbatim.

#define B_    8
#define CIN_  4
#define H_    64
#define W_    64
#define OUT_  8
#define K2_   9
#define G_    8
#define HO_   62
#define WO_   62
#define R2_   39.0625f     // R^2 folded into weights

#define TILW  36
#define TILH  10
#define NPOS  (TILH*TILW)  // 360
#define PSTR  360          // A-frag banks 8*tg+gid all distinct
#define NTHR  512

#define TSH_F (32 * PSTR)                    // 11520 floats per copy
#define WHF   (32 * K2_ * OUT_)              // 2304 floats per copy
#define SMEM_FLOATS (2 * TSH_F + 2 * WHF + 8)
#define SMEM_BYTES  (SMEM_FLOATS * 4)        // 110,624 B

__device__ __forceinline__ uint32_t f2tf32(float v) {
    uint32_t r;
    asm("cvt.rna.tf32.f32 %0, %1;" : "=r"(r) : "f"(v));
    return r;
}

__device__ __forceinline__ void mma_tf32(float& c0, float& c1, float& c2, float& c3,
                                         uint32_t a0, uint32_t a1, uint32_t a2, uint32_t a3,
                                         uint32_t b0, uint32_t b1) {
    asm volatile(
        "mma.sync.aligned.m16n8k8.row.col.f32.tf32.tf32.f32 "
        "{%0,%1,%2,%3},{%4,%5,%6,%7},{%8,%9},{%0,%1,%2,%3};"
        : "+f"(c0), "+f"(c1), "+f"(c2), "+f"(c3)
        : "r"(a0), "r"(a1), "r"(a2), "r"(a3), "r"(b0), "r"(b1));
}

__global__ void __launch_bounds__(NTHR, 1)
kan_fused_kernel(const float* __restrict__ x,
                 const float* __restrict__ phase_low,
                 const float* __restrict__ phase_high,
                 const float* __restrict__ weight,
                 const float* __restrict__ bias,
                 float* __restrict__ out) {
    extern __shared__ __align__(16) float smem[];
    float* th  = smem;                 // t-planes, tf32 hi
    float* tl  = th + TSH_F;           // t-planes, tf32 lo
    float* wh  = tl + TSH_F;           // weights*R^2, tf32 hi  [plane][f][o]
    float* wl  = wh + WHF;             // weights*R^2, tf32 lo
    float* bsh = wl + WHF;             // bias sums

    const int b   = blockIdx.z;
    const int x0  = blockIdx.x * 32;
    const int y0  = blockIdx.y * 8;
    const int tid = threadIdx.x;

    // ======== prologue: all global loads up front ========
    float xreg[3];
#pragma unroll
    for (int it = 0; it < 3; it++) {
        int i = tid + it * NTHR;
        float xv = 0.0f;
        if (i < CIN_ * NPOS) {
            int c   = i / NPOS;
            int pos = i - c * NPOS;
            int row = pos / TILW;
            int col = pos - row * TILW;
            int gy = y0 + row, gx = x0 + col;
            if (gy < H_ && gx < W_)
                xv = __ldg(&x[((b * CIN_ + c) * H_ + gy) * W_ + gx]);
        }
        xreg[it] = xv;
    }

    // weights, coalesced: flat i = o*288 + c*72 + f*8 + g; dst = plane*72 + f*8 + o
#pragma unroll
    for (int it = 0; it < 5; it++) {
        int i = tid + it * NTHR;
        if (i < WHF) {
            float wv = __ldg(&weight[i]) * R2_;
            int g  = i & 7;
            int f  = (i >> 3) % K2_;
            int c  = (i / 72) & 3;
            int o  = i / 288;
            int dst = (c * 8 + g) * (K2_ * OUT_) + f * OUT_ + o;
            uint32_t hi = f2tf32(wv);
            float lof = wv - __uint_as_float(hi);
            wh[dst] = __uint_as_float(hi);
            wl[dst] = __uint_as_float(f2tf32(lof));
        }
    }
    if (tid < OUT_) {
        float s = 0.0f;
#pragma unroll
        for (int c = 0; c < CIN_; c++) s += bias[tid * CIN_ + c];
        bsh[tid] = s;
    }

    float pl[G_];
#pragma unroll
    for (int g = 0; g < G_; g++)
        pl[g] = __ldg(&phase_low[g]);   // broadcast arrays; ph = pl + 0.8

    // ---- spline fill, hi/lo tf32 split (from registers; no DRAM wait)
#pragma unroll
    for (int it = 0; it < 3; it++) {
        int i = tid + it * NTHR;
        if (i < CIN_ * NPOS) {
            int c   = i / NPOS;
            int pos = i - c * NPOS;
            float xv = xreg[it];
#pragma unroll
            for (int g = 0; g < G_; g++) {
                float a = xv - pl[g];
                float d = 0.8f - a;
                float m = fmaxf(a * d, 0.0f);
                float t = m * m;                       // R^2 lives in weights
                uint32_t hi = f2tf32(t);
                float lof = t - __uint_as_float(hi);
                int idx = (c * G_ + g) * PSTR + pos;
                th[idx] = __uint_as_float(hi);
                tl[idx] = __uint_as_float(f2tf32(lof));
            }
        }
    }
    __syncthreads();   // the ONLY barrier

    // ---- GEMM via mma.m16n8k8 tf32, 3xTF32; one 16-px M-tile per warp
    const int w   = tid >> 5;            // warp 0..15
    const int wl_ = w & 7;               // output row y0 + wl_
    const int h   = w >> 3;              // M-tile half: px block 16*h
    const int l   = tid & 31;
    const int gid = l >> 2;              // fragment groupID
    const int tg  = l & 3;               // fragment threadID_in_group

    // A-fragment: addr = plane*PSTR + (wl_+fi)*TILW + 16*h + px + fj
    const int ac = tg * PSTR + wl_ * TILW + 16 * h + gid;
    // B-fragment: addr = (pg*8+tg)*72 + f*8 + gid
    const int bc = tg * (K2_ * OUT_) + gid;

    float c0 = 0.f, c1 = 0.f, c2 = 0.f, c3 = 0.f;

#pragma unroll
    for (int pg = 0; pg < 4; pg++) {     // plane group = input channel
#pragma unroll
        for (int f = 0; f < 9; f++) {    // filter tap fi*3+fj
            const int fi = f / 3, fj = f % 3;
            const int a  = ac + pg * (8 * PSTR) + fi * TILW + fj;
            const int bo = bc + pg * (8 * K2_ * OUT_) + f * OUT_;

            uint32_t bh0 = __float_as_uint(wh[bo]);
            uint32_t bh1 = __float_as_uint(wh[bo + 4 * K2_ * OUT_]);
            uint32_t bl0 = __float_as_uint(wl[bo]);
            uint32_t bl1 = __float_as_uint(wl[bo + 4 * K2_ * OUT_]);

            uint32_t ah0 = __float_as_uint(th[a]);
            uint32_t ah1 = __float_as_uint(th[a + 8]);
            uint32_t ah2 = __float_as_uint(th[a + 4 * PSTR]);
            uint32_t ah3 = __float_as_uint(th[a + 4 * PSTR + 8]);
            uint32_t al0 = __float_as_uint(tl[a]);
            uint32_t al1 = __float_as_uint(tl[a + 8]);
            uint32_t al2 = __float_as_uint(tl[a + 4 * PSTR]);
            uint32_t al3 = __float_as_uint(tl[a + 4 * PSTR + 8]);

            mma_tf32(c0, c1, c2, c3, ah0, ah1, ah2, ah3, bh0, bh1);   // hi*hi
            mma_tf32(c0, c1, c2, c3, al0, al1, al2, al3, bh0, bh1);   // lo*hi
            mma_tf32(c0, c1, c2, c3, ah0, ah1, ah2, ah3, bl0, bl1);   // hi*lo
        }
    }

    // ---- epilogue: C fragment -> out (+bias), guarded
    // c0: (px = 16*h+gid, o = 2*tg), c1: o+1, c2: px+8 o, c3: px+8 o+1
    const int oy = y0 + wl_;
    if (oy < HO_) {
        const int o0 = 2 * tg;
        const float b0v = bsh[o0];
        const float b1v = bsh[o0 + 1];
        const long strideO = (long)HO_ * WO_;
        float* baseA = out + ((long)(b * OUT_ + o0) * HO_ + oy) * WO_;
        float* baseB = baseA + strideO;   // o0+1
        int px0 = x0 + 16 * h + gid;
        int px1 = px0 + 8;
        if (px0 < WO_) {
            baseA[px0] = c0 + b0v;
            baseB[px0] = c1 + b1v;
        }
        if (px1 < WO_) {
            baseA[px1] = c2 + b0v;
            baseB[px1] = c3 + b1v;
        }
    }
}

// ---------------------------------------------------------------------------
extern "C" void kernel_launch(void* const* d_in, const int* in_sizes, int n_in,
                              void* d_out, int out_size) {
    const float* x          = (const float*)d_in[0];
    const float* phase_low  = (const float*)d_in[1];
    const float* phase_high = (const float*)d_in[2];
    const float* weight     = (const float*)d_in[3];
    const float* bias       = (const float*)d_in[4];
    float* out = (float*)d_out;

    static int attr_set = 0;   // idempotent host-side attribute (no device alloc)
    if (!attr_set) {
        cudaFuncSetAttribute(kan_fused_kernel,
                             cudaFuncAttributeMaxDynamicSharedMemorySize,
                             SMEM_BYTES);
        attr_set = 1;
    }

    dim3 grid(2, 8, B_);                 // 128 blocks x 512 threads
    kan_fused_kernel<<<grid, NTHR, SMEM_BYTES>>>(x, phase_low, phase_high,
                                                 weight, bias, out);
}